// round 1
// baseline (speedup 1.0000x reference)
#include <cuda_runtime.h>
#include <cuda_bf16.h>
#include <cstdint>

// Problem constants
#define BATCH  16
#define C_IN   32
#define H_IN   224
#define N_FILT 64
#define KS     5
#define H_OUT  220   // 224 - 5 + 1

// Tiling
#define BF     16            // filters per block
#define TILE   32            // output tile edge
#define IN_T   36            // TILE + KS - 1
#define NTILE  7             // ceil(220/32)

__device__ __forceinline__ unsigned long long pack2(float v) {
    unsigned long long r;
    asm("mov.b64 %0, {%1, %1};" : "=l"(r) : "r"(__float_as_uint(v)));
    return r;
}

__device__ __forceinline__ void ffma2(unsigned long long& acc,
                                      unsigned long long a,
                                      unsigned long long b) {
    // packed fp32 FMA (Blackwell): two exact fp32 FMAs per instruction
    asm("fma.rn.f32x2 %0, %1, %2, %0;" : "+l"(acc) : "l"(a), "l"(b));
}

__global__ __launch_bounds__(256, 2)
void conv5x5_kernel(const float* __restrict__ x,
                    const float* __restrict__ w,
                    const float* __restrict__ bias,
                    float* __restrict__ out)
{
    __shared__ __align__(16) float s_in[IN_T][IN_T + 1];   // padded rows: conflict-free
    __shared__ __align__(16) float s_w[KS * KS][BF];       // [k][filter], pairs 8B-aligned

    const int tx = threadIdx.x & 15;
    const int ty = threadIdx.x >> 4;
    const int tile_x = (blockIdx.x % NTILE) * TILE;
    const int tile_y = (blockIdx.x / NTILE) * TILE;
    const int fb = blockIdx.y * BF;
    const int b  = blockIdx.z;

    // acc[dy][dx][pair] : pixel (tile_y + dy*16 + ty, tile_x + dx*16 + tx),
    // filters (fb + 2p, fb + 2p + 1) packed as f32x2
    unsigned long long acc[2][2][BF / 2];
    #pragma unroll
    for (int i = 0; i < 2; ++i)
        #pragma unroll
        for (int j = 0; j < 2; ++j)
            #pragma unroll
            for (int p = 0; p < BF / 2; ++p)
                acc[i][j][p] = 0ULL;

    const float* xb = x + (size_t)b * C_IN * H_IN * H_IN;

    for (int c = 0; c < C_IN; ++c) {
        // ---- stage input tile (36x36, zero-padded at image edge) ----
        const float* xc = xb + (size_t)c * H_IN * H_IN;
        for (int i = threadIdx.x; i < IN_T * IN_T; i += 256) {
            int r   = i / IN_T;
            int col = i - r * IN_T;
            int gy = tile_y + r, gx = tile_x + col;
            float v = 0.0f;
            if (gy < H_IN && gx < H_IN) v = xc[gy * H_IN + gx];
            s_in[r][col] = v;
        }
        // ---- stage weights for 16 filters, this channel ----
        for (int i = threadIdx.x; i < BF * KS * KS; i += 256) {
            int k = i / BF;
            int f = i - k * BF;
            s_w[k][f] = w[((size_t)(fb + f) * C_IN + c) * (KS * KS) + k];
        }
        __syncthreads();

        // ---- main compute ----
        #pragma unroll
        for (int kh = 0; kh < KS; ++kh) {
            #pragma unroll
            for (int kw = 0; kw < KS; ++kw) {
                const int k = kh * KS + kw;
                unsigned long long in2[2][2];
                #pragma unroll
                for (int dy = 0; dy < 2; ++dy)
                    #pragma unroll
                    for (int dx = 0; dx < 2; ++dx)
                        in2[dy][dx] = pack2(s_in[dy * 16 + ty + kh][dx * 16 + tx + kw]);

                #pragma unroll
                for (int p = 0; p < BF / 2; ++p) {
                    unsigned long long w2 =
                        *reinterpret_cast<const unsigned long long*>(&s_w[k][2 * p]);
                    ffma2(acc[0][0][p], in2[0][0], w2);
                    ffma2(acc[0][1][p], in2[0][1], w2);
                    ffma2(acc[1][0][p], in2[1][0], w2);
                    ffma2(acc[1][1][p], in2[1][1], w2);
                }
            }
        }
        __syncthreads();
    }

    // ---- epilogue: unpack, add bias, guarded store ----
    #pragma unroll
    for (int dy = 0; dy < 2; ++dy) {
        int oy = tile_y + dy * 16 + ty;
        if (oy >= H_OUT) continue;
        #pragma unroll
        for (int dx = 0; dx < 2; ++dx) {
            int ox = tile_x + dx * 16 + tx;
            if (ox >= H_OUT) continue;
            #pragma unroll
            for (int p = 0; p < BF / 2; ++p) {
                unsigned int lo, hi;
                asm("mov.b64 {%0, %1}, %2;" : "=r"(lo), "=r"(hi) : "l"(acc[dy][dx][p]));
                int f0 = fb + 2 * p;
                out[(((size_t)b * N_FILT + f0) * H_OUT + oy) * H_OUT + ox] =
                    __uint_as_float(lo) + bias[f0];
                out[(((size_t)b * N_FILT + f0 + 1) * H_OUT + oy) * H_OUT + ox] =
                    __uint_as_float(hi) + bias[f0 + 1];
            }
        }
    }
}

extern "C" void kernel_launch(void* const* d_in, const int* in_sizes, int n_in,
                              void* d_out, int out_size) {
    const float* x    = (const float*)d_in[0];
    const float* w    = (const float*)d_in[1];
    const float* bias = (const float*)d_in[2];
    float* out = (float*)d_out;

    dim3 grid(NTILE * NTILE, N_FILT / BF, BATCH);
    conv5x5_kernel<<<grid, 256>>>(x, w, bias, out);
}

// round 2
// speedup vs baseline: 1.0040x; 1.0040x over previous
#include <cuda_runtime.h>
#include <cuda_bf16.h>
#include <cstdint>

// Problem constants
#define BATCH  16
#define C_IN   32
#define H_IN   224
#define N_FILT 64
#define KS     5
#define H_OUT  220   // 224 - 5 + 1

// Tiling
#define BF     16            // filters per block
#define TILE   32            // output tile edge
#define IN_T   36            // TILE + KS - 1
#define NTILE  7             // ceil(220/32)

__device__ __forceinline__ unsigned long long pack2(float v) {
    unsigned long long r;
    asm("mov.b64 %0, {%1, %1};" : "=l"(r) : "r"(__float_as_uint(v)));
    return r;
}

__device__ __forceinline__ void ffma2(unsigned long long& acc,
                                      unsigned long long a,
                                      unsigned long long b) {
    // packed fp32 FMA (Blackwell): two exact fp32 FMAs per instruction
    asm("fma.rn.f32x2 %0, %1, %2, %0;" : "+l"(acc) : "l"(a), "l"(b));
}

__global__ __launch_bounds__(256, 2)
void conv5x5_kernel(const float* __restrict__ x,
                    const float* __restrict__ w,
                    const float* __restrict__ bias,
                    float* __restrict__ out)
{
    __shared__ __align__(16) float s_in[IN_T][IN_T + 1];   // padded rows: conflict-free
    __shared__ __align__(16) float s_w[KS * KS][BF];       // [k][filter], pairs 8B-aligned

    const int tx = threadIdx.x & 15;
    const int ty = threadIdx.x >> 4;
    const int tile_x = (blockIdx.x % NTILE) * TILE;
    const int tile_y = (blockIdx.x / NTILE) * TILE;
    const int fb = blockIdx.y * BF;
    const int b  = blockIdx.z;

    // acc[dy][dx][pair] : pixel (tile_y + dy*16 + ty, tile_x + dx*16 + tx),
    // filters (fb + 2p, fb + 2p + 1) packed as f32x2
    unsigned long long acc[2][2][BF / 2];
    #pragma unroll
    for (int i = 0; i < 2; ++i)
        #pragma unroll
        for (int j = 0; j < 2; ++j)
            #pragma unroll
            for (int p = 0; p < BF / 2; ++p)
                acc[i][j][p] = 0ULL;

    const float* xb = x + (size_t)b * C_IN * H_IN * H_IN;

    for (int c = 0; c < C_IN; ++c) {
        // ---- stage input tile (36x36, zero-padded at image edge) ----
        const float* xc = xb + (size_t)c * H_IN * H_IN;
        for (int i = threadIdx.x; i < IN_T * IN_T; i += 256) {
            int r   = i / IN_T;
            int col = i - r * IN_T;
            int gy = tile_y + r, gx = tile_x + col;
            float v = 0.0f;
            if (gy < H_IN && gx < H_IN) v = xc[gy * H_IN + gx];
            s_in[r][col] = v;
        }
        // ---- stage weights for 16 filters, this channel ----
        for (int i = threadIdx.x; i < BF * KS * KS; i += 256) {
            int k = i / BF;
            int f = i - k * BF;
            s_w[k][f] = w[((size_t)(fb + f) * C_IN + c) * (KS * KS) + k];
        }
        __syncthreads();

        // ---- main compute ----
        #pragma unroll
        for (int kh = 0; kh < KS; ++kh) {
            #pragma unroll
            for (int kw = 0; kw < KS; ++kw) {
                const int k = kh * KS + kw;
                unsigned long long in2[2][2];
                #pragma unroll
                for (int dy = 0; dy < 2; ++dy)
                    #pragma unroll
                    for (int dx = 0; dx < 2; ++dx)
                        in2[dy][dx] = pack2(s_in[dy * 16 + ty + kh][dx * 16 + tx + kw]);

                #pragma unroll
                for (int p = 0; p < BF / 2; ++p) {
                    unsigned long long w2 =
                        *reinterpret_cast<const unsigned long long*>(&s_w[k][2 * p]);
                    ffma2(acc[0][0][p], in2[0][0], w2);
                    ffma2(acc[0][1][p], in2[0][1], w2);
                    ffma2(acc[1][0][p], in2[1][0], w2);
                    ffma2(acc[1][1][p], in2[1][1], w2);
                }
            }
        }
        __syncthreads();
    }

    // ---- epilogue: unpack, add bias, guarded store ----
    #pragma unroll
    for (int dy = 0; dy < 2; ++dy) {
        int oy = tile_y + dy * 16 + ty;
        if (oy >= H_OUT) continue;
        #pragma unroll
        for (int dx = 0; dx < 2; ++dx) {
            int ox = tile_x + dx * 16 + tx;
            if (ox >= H_OUT) continue;
            #pragma unroll
            for (int p = 0; p < BF / 2; ++p) {
                unsigned int lo, hi;
                asm("mov.b64 {%0, %1}, %2;" : "=r"(lo), "=r"(hi) : "l"(acc[dy][dx][p]));
                int f0 = fb + 2 * p;
                out[(((size_t)b * N_FILT + f0) * H_OUT + oy) * H_OUT + ox] =
                    __uint_as_float(lo) + bias[f0];
                out[(((size_t)b * N_FILT + f0 + 1) * H_OUT + oy) * H_OUT + ox] =
                    __uint_as_float(hi) + bias[f0 + 1];
            }
        }
    }
}

extern "C" void kernel_launch(void* const* d_in, const int* in_sizes, int n_in,
                              void* d_out, int out_size) {
    const float* x    = (const float*)d_in[0];
    const float* w    = (const float*)d_in[1];
    const float* bias = (const float*)d_in[2];
    float* out = (float*)d_out;

    dim3 grid(NTILE * NTILE, N_FILT / BF, BATCH);
    conv5x5_kernel<<<grid, 256>>>(x, w, bias, out);
}

// round 3
// speedup vs baseline: 1.3581x; 1.3527x over previous
#include <cuda_runtime.h>
#include <cuda_bf16.h>
#include <cstdint>

#define BATCH  16
#define C_IN   32
#define H_IN   224
#define N_FILT 64
#define KS     5
#define H_OUT  220

#define BF     16            // filters per block
#define TILE   32            // output tile edge
#define IN_T   36            // TILE + KS - 1
#define IN_STR 40            // smem row stride (16B-aligned rows)
#define NTILE  7

using u64 = unsigned long long;

__device__ __forceinline__ u64 pack2(float v) {
    u64 r;
    asm("mov.b64 %0, {%1, %1};" : "=l"(r) : "r"(__float_as_uint(v)));
    return r;
}
__device__ __forceinline__ void ffma2(u64& acc, u64 a, u64 b) {
    asm("fma.rn.f32x2 %0, %1, %2, %0;" : "+l"(acc) : "l"(a), "l"(b));
}
__device__ __forceinline__ uint32_t sptr(const void* p) {
    return (uint32_t)__cvta_generic_to_shared(p);
}
__device__ __forceinline__ void cpa16(void* s, const void* g) {
    asm volatile("cp.async.ca.shared.global [%0], [%1], 16;" :: "r"(sptr(s)), "l"(g));
}
__device__ __forceinline__ void cpa4(void* s, const void* g) {
    asm volatile("cp.async.ca.shared.global [%0], [%1], 4;" :: "r"(sptr(s)), "l"(g));
}
__device__ __forceinline__ void cp_commit() { asm volatile("cp.async.commit_group;"); }
template<int N>
__device__ __forceinline__ void cp_wait() { asm volatile("cp.async.wait_group %0;" :: "n"(N)); }

__global__ __launch_bounds__(256, 2)
void conv5x5_kernel(const float* __restrict__ x,
                    const float* __restrict__ w,
                    const float* __restrict__ bias,
                    float* __restrict__ out)
{
    __shared__ __align__(16) float s_in[2][IN_T][IN_STR];   // 11520 B
    __shared__ __align__(16) float s_w[2][KS * KS][BF];     //  3200 B

    const int tid = threadIdx.x;
    const int tx8 = tid & 7;          // 8 x-groups of 4 px
    const int ty  = tid >> 3;         // 32 y rows
    const int x0  = tx8 * 4;
    const int tile_x = (blockIdx.x % NTILE) * TILE;
    const int tile_y = (blockIdx.x / NTILE) * TILE;
    const int fb = blockIdx.y * BF;
    const int b  = blockIdx.z;
    const bool interior = (tile_x + IN_T <= H_IN) && (tile_y + IN_T <= H_IN);

    const float* xb = x + (size_t)b * C_IN * H_IN * H_IN;

    // Edge tiles: OOB pattern is channel-invariant — zero-fill those slots ONCE
    // in both buffers; staging below only writes in-bounds elements.
    if (!interior) {
        for (int i = tid; i < IN_T * IN_T; i += 256) {
            int r = i / IN_T, col = i - r * IN_T;
            if (tile_y + r >= H_IN || tile_x + col >= H_IN) {
                s_in[0][r][col] = 0.0f;
                s_in[1][r][col] = 0.0f;
            }
        }
    }

    auto stage = [&](int c, int buf) {
        const float* xc = xb + (size_t)c * H_IN * H_IN;
        if (interior) {
            // 36 rows x 9 float4; gmem row start is 128B-aligned (tile_x % 32 == 0)
            for (int i = tid; i < IN_T * 9; i += 256) {
                int r = i / 9, q = i - r * 9;
                cpa16(&s_in[buf][r][q * 4], xc + (tile_y + r) * H_IN + tile_x + q * 4);
            }
        } else {
            for (int i = tid; i < IN_T * IN_T; i += 256) {
                int r = i / IN_T, col = i - r * IN_T;
                int gy = tile_y + r, gx = tile_x + col;
                if (gy < H_IN && gx < H_IN)
                    cpa4(&s_in[buf][r][col], xc + gy * H_IN + gx);
            }
        }
        for (int i = tid; i < BF * KS * KS; i += 256) {
            int k = i >> 4, f = i & 15;
            cpa4(&s_w[buf][k][f], &w[((size_t)(fb + f) * C_IN + c) * (KS * KS) + k]);
        }
        cp_commit();
    };

    // acc[px][pair]: output pixel (tile_y+ty, tile_x+x0+px), filters (fb+2p, fb+2p+1)
    u64 acc[4][8];
    #pragma unroll
    for (int i = 0; i < 4; ++i)
        #pragma unroll
        for (int p = 0; p < 8; ++p)
            acc[i][p] = 0ULL;

    stage(0, 0);

    for (int c = 0; c < C_IN; ++c) {
        const int buf = c & 1;
        if (c + 1 < C_IN) { stage(c + 1, buf ^ 1); cp_wait<1>(); }
        else              { cp_wait<0>(); }
        __syncthreads();

        const float (*si)[IN_STR] = s_in[buf];
        #pragma unroll
        for (int kh = 0; kh < KS; ++kh) {
            // register sliding window: 8 inputs serve all (kw, px) combos this row
            const float* row = &si[ty + kh][x0];
            float4 av = *reinterpret_cast<const float4*>(row);
            float4 bv = *reinterpret_cast<const float4*>(row + 4);
            u64 rb[8] = { pack2(av.x), pack2(av.y), pack2(av.z), pack2(av.w),
                          pack2(bv.x), pack2(bv.y), pack2(bv.z), pack2(bv.w) };
            #pragma unroll
            for (int kw = 0; kw < KS; ++kw) {
                const int k = kh * KS + kw;
                #pragma unroll
                for (int p = 0; p < 8; ++p) {
                    u64 w2 = *reinterpret_cast<const u64*>(&s_w[buf][k][2 * p]);
                    ffma2(acc[0][p], rb[kw + 0], w2);
                    ffma2(acc[1][p], rb[kw + 1], w2);
                    ffma2(acc[2][p], rb[kw + 2], w2);
                    ffma2(acc[3][p], rb[kw + 3], w2);
                }
            }
        }
        __syncthreads();   // protect buf before it is re-staged at c+2
    }

    // ---- epilogue ----
    const int oy = tile_y + ty;
    if (oy >= H_OUT) return;
    const int ox = tile_x + x0;
    if (ox >= H_OUT) return;
    const bool full = (ox + 3 < H_OUT);

    #pragma unroll
    for (int p = 0; p < 8; ++p) {
        const int f0 = fb + 2 * p;
        const float b0 = bias[f0], b1 = bias[f0 + 1];
        float v0[4], v1[4];
        #pragma unroll
        for (int px = 0; px < 4; ++px) {
            unsigned int lo, hi;
            asm("mov.b64 {%0, %1}, %2;" : "=r"(lo), "=r"(hi) : "l"(acc[px][p]));
            v0[px] = __uint_as_float(lo) + b0;
            v1[px] = __uint_as_float(hi) + b1;
        }
        float* d0 = out + (((size_t)b * N_FILT + f0    ) * H_OUT + oy) * H_OUT + ox;
        float* d1 = out + (((size_t)b * N_FILT + f0 + 1) * H_OUT + oy) * H_OUT + ox;
        if (full) {
            *reinterpret_cast<float4*>(d0) = make_float4(v0[0], v0[1], v0[2], v0[3]);
            *reinterpret_cast<float4*>(d1) = make_float4(v1[0], v1[1], v1[2], v1[3]);
        } else {
            #pragma unroll
            for (int px = 0; px < 4; ++px) {
                if (ox + px < H_OUT) { d0[px] = v0[px]; d1[px] = v1[px]; }
            }
        }
    }
}

extern "C" void kernel_launch(void* const* d_in, const int* in_sizes, int n_in,
                              void* d_out, int out_size) {
    const float* x    = (const float*)d_in[0];
    const float* w    = (const float*)d_in[1];
    const float* bias = (const float*)d_in[2];
    float* out = (float*)d_out;

    dim3 grid(NTILE * NTILE, N_FILT / BF, BATCH);
    conv5x5_kernel<<<grid, 256>>>(x, w, bias, out);
}

// round 5
// speedup vs baseline: 3.1766x; 2.3390x over previous
#include <cuda_runtime.h>
#include <cuda_bf16.h>
#include <cstdint>

#define H_IN   224
#define H_OUT  220
#define C_IN   32
#define N_FILT 64
#define KS     5
#define NTAP   25
#define BATCH  16

// CTA output tile: 8 rows x 32 cols = 256 pixels (M), N = 64 filters
#define TR 8
#define TC 32
#define HR 12              // TR + 4
#define HC 36              // TC + 4
#define NLINES (HR * HC)   // 432 halo pixels
#define NTX 7              // ceil(220/32)
#define NTY 28             // ceil(220/8)

// SMEM: A halo [line][ah(32)|al(32)] bf16, 128B data padded to 144B rows
#define ASTRIDE 144
#define A_BYTES (NLINES * ASTRIDE)      // 62208
// B per tap: [k'=96][n=64] bf16, 128B rows padded to 144B, double buffered
#define BROWS   96
#define BSTRIDE 144
#define B_TILE  (BROWS * BSTRIDE)       // 13824
#define B_OFF   A_BYTES
#define SMEM_BYTES (B_OFF + 2 * B_TILE) // 89856

__device__ __nv_bfloat16 g_wb[NTAP * BROWS * N_FILT];   // [tap][k'][f], 300KB

// ---------------- helpers ----------------
__device__ __forceinline__ uint32_t smem_u32(const void* p) {
    uint32_t a;
    asm("{ .reg .u64 t; cvta.to.shared.u64 t, %1; cvt.u32.u64 %0, t; }" : "=r"(a) : "l"(p));
    return a;
}
__device__ __forceinline__ void cpa16(uint32_t s, const void* g) {
    asm volatile("cp.async.ca.shared.global [%0], [%1], 16;" :: "r"(s), "l"(g));
}
__device__ __forceinline__ void cp_commit() { asm volatile("cp.async.commit_group;"); }
template<int N>
__device__ __forceinline__ void cp_wait() { asm volatile("cp.async.wait_group %0;" :: "n"(N)); }

__device__ __forceinline__ void ldsm4(uint32_t* r, uint32_t a) {
    asm volatile("ldmatrix.sync.aligned.m8n8.x4.shared.b16 {%0,%1,%2,%3}, [%4];"
                 : "=r"(r[0]), "=r"(r[1]), "=r"(r[2]), "=r"(r[3]) : "r"(a));
}
__device__ __forceinline__ void ldsm4t(uint32_t* r, uint32_t a) {
    asm volatile("ldmatrix.sync.aligned.m8n8.x4.trans.shared.b16 {%0,%1,%2,%3}, [%4];"
                 : "=r"(r[0]), "=r"(r[1]), "=r"(r[2]), "=r"(r[3]) : "r"(a));
}
__device__ __forceinline__ void mma16816(float* d, const uint32_t* a,
                                         uint32_t b0, uint32_t b1) {
    asm volatile(
        "mma.sync.aligned.m16n8k16.row.col.f32.bf16.bf16.f32 "
        "{%0,%1,%2,%3}, {%4,%5,%6,%7}, {%8,%9}, {%0,%1,%2,%3};"
        : "+f"(d[0]), "+f"(d[1]), "+f"(d[2]), "+f"(d[3])
        : "r"(a[0]), "r"(a[1]), "r"(a[2]), "r"(a[3]), "r"(b0), "r"(b1));
}
__device__ __forceinline__ void sts16(uint32_t a, unsigned short v) {
    asm volatile("st.shared.u16 [%0], %1;" :: "r"(a), "h"(v));
}

// ---------------- prep: split weights into bf16 hi/lo, K'-extended layout ----
// rows 0-31: hi(c) ; rows 32-63: hi(c) duplicate ; rows 64-95: lo(c)
__global__ void prep_weights(const float* __restrict__ w) {
    int idx = blockIdx.x * blockDim.x + threadIdx.x;
    if (idx >= NTAP * BROWS * N_FILT) return;
    int tap = idx / (BROWS * N_FILT);
    int rem = idx - tap * (BROWS * N_FILT);
    int kp = rem >> 6, f = rem & 63;
    int c = kp & 31;
    float v = w[(f * C_IN + c) * (KS * KS) + tap];
    __nv_bfloat16 hi = __float2bfloat16(v);
    __nv_bfloat16 outv = hi;
    if (kp >= 64) outv = __float2bfloat16(v - __bfloat162float(hi));
    g_wb[idx] = outv;
}

// ---------------- main kernel ----------------
__global__ __launch_bounds__(256, 2)
void conv_mma_kernel(const float* __restrict__ x,
                     const float* __restrict__ bias,
                     float* __restrict__ out)
{
    extern __shared__ __align__(128) char smem[];
    const uint32_t sb = smem_u32(smem);

    const int tid = threadIdx.x;
    const int wid = tid >> 5, lid = tid & 31;
    const int g = lid >> 2, c4 = lid & 3;

    const int x0 = blockIdx.x * TC;
    const int y0 = blockIdx.y * TR;
    const int b  = blockIdx.z;

    // stage B tile for a tap into buf
    auto stageB = [&](int tap, int buf) {
        const __nv_bfloat16* src0 = g_wb + (size_t)tap * BROWS * N_FILT;
        #pragma unroll
        for (int j = 0; j < 3; ++j) {
            int i = tid + j * 256;                 // 768 chunks of 16B
            int row = i >> 3, seg = i & 7;
            cpa16(sb + B_OFF + buf * B_TILE + row * BSTRIDE + seg * 16,
                  src0 + row * N_FILT + seg * 8);
        }
        cp_commit();
    };

    stageB(0, 0);   // overlap tap-0 B load with A build

    // ---- build A halo once: fp32 -> bf16 hi/lo ----
    {
        const float* xb = x + (size_t)b * C_IN * H_IN * H_IN;
        #pragma unroll
        for (int j = 0; j < (NLINES * C_IN) / 256; ++j) {   // 54 iters
            int idx = tid + j * 256;
            int c   = idx / NLINES;
            int line = idx - c * NLINES;
            int hy = line / HC, hx = line - hy * HC;
            int gy = y0 + hy, gx = x0 + hx;
            float v = 0.0f;
            if (gy < H_IN && gx < H_IN)
                v = xb[((size_t)c * H_IN + gy) * H_IN + gx];
            __nv_bfloat16 hi = __float2bfloat16(v);
            __nv_bfloat16 lo = __float2bfloat16(v - __bfloat162float(hi));
            uint32_t base = sb + line * ASTRIDE + c * 2;
            sts16(base,      __bfloat16_as_ushort(hi));
            sts16(base + 64, __bfloat16_as_ushort(lo));
        }
    }
    __syncthreads();

    // accumulators: [m-block][n-subtile][4]
    float acc[2][8][4];
    #pragma unroll
    for (int mb = 0; mb < 2; ++mb)
        #pragma unroll
        for (int ns = 0; ns < 8; ++ns)
            #pragma unroll
            for (int q = 0; q < 4; ++q) acc[mb][ns][q] = 0.0f;

    // lane-invariant parts of ldmatrix addresses
    const int lrow = lid & 15;              // row within 16-row block
    const int lcol = lid >> 4;              // 0/1 -> col-half
    const uint32_t b_lane = sb + B_OFF + lrow * BSTRIDE + lcol * 16;

    uint32_t a01[2][2][4];                  // saved A frags for k-steps 0,1

    for (int tap = 0; tap < NTAP; ++tap) {
        const int buf = tap & 1;
        if (tap + 1 < NTAP) { stageB(tap + 1, buf ^ 1); cp_wait<1>(); }
        else                { cp_wait<0>(); }
        __syncthreads();

        const int kh = tap / 5, kw = tap - kh * 5;
        // warp w covers tile row w; A row i -> halo line (w+kh)*36 + kw + i
        const uint32_t a_lane = sb + (uint32_t)(((wid + kh) * HC + kw + lrow) * ASTRIDE)
                              + lcol * 16;
        const uint32_t b_tap = b_lane + buf * B_TILE;

        #pragma unroll
        for (int kk = 0; kk < 6; ++kk) {
            uint32_t afr[2][4];
            if (kk < 4) {
                ldsm4(afr[0], a_lane + kk * 32);
                ldsm4(afr[1], a_lane + 16 * ASTRIDE + kk * 32);
                if (kk < 2) {
                    #pragma unroll
                    for (int mb = 0; mb < 2; ++mb)
                        #pragma unroll
                        for (int q = 0; q < 4; ++q) a01[kk][mb][q] = afr[mb][q];
                }
            } else {
                #pragma unroll
                for (int mb = 0; mb < 2; ++mb)
                    #pragma unroll
                    for (int q = 0; q < 4; ++q) afr[mb][q] = a01[kk - 4][mb][q];
            }
            #pragma unroll
            for (int np = 0; np < 4; ++np) {
                uint32_t bfr[4];
                ldsm4t(bfr, b_tap + kk * 16 * BSTRIDE + np * 32);
                mma16816(acc[0][2 * np + 0], afr[0], bfr[0], bfr[1]);
                mma16816(acc[0][2 * np + 1], afr[0], bfr[2], bfr[3]);
                mma16816(acc[1][2 * np + 0], afr[1], bfr[0], bfr[1]);
                mma16816(acc[1][2 * np + 1], afr[1], bfr[2], bfr[3]);
            }
        }
        __syncthreads();
    }

    // ---- epilogue ----
    const int oy = y0 + wid;
    if (oy >= H_OUT) return;

    float bv[8][2];
    #pragma unroll
    for (int ns = 0; ns < 8; ++ns) {
        bv[ns][0] = bias[ns * 8 + 2 * c4];
        bv[ns][1] = bias[ns * 8 + 2 * c4 + 1];
    }

    #pragma unroll
    for (int mb = 0; mb < 2; ++mb) {
        #pragma unroll
        for (int h = 0; h < 2; ++h) {
            int i = mb * 16 + h * 8 + g;
            int ox = x0 + i;
            if (ox >= H_OUT) continue;
            size_t base = (((size_t)b * N_FILT) * H_OUT + oy) * H_OUT + ox;
            #pragma unroll
            for (int ns = 0; ns < 8; ++ns) {
                int f = ns * 8 + 2 * c4;
                out[base + (size_t)f * H_OUT * H_OUT] =
                    acc[mb][ns][2 * h + 0] + bv[ns][0];
                out[base + (size_t)(f + 1) * H_OUT * H_OUT] =
                    acc[mb][ns][2 * h + 1] + bv[ns][1];
            }
        }
    }
}

extern "C" void kernel_launch(void* const* d_in, const int* in_sizes, int n_in,
                              void* d_out, int out_size) {
    const float* x    = (const float*)d_in[0];
    const float* w    = (const float*)d_in[1];
    const float* bias = (const float*)d_in[2];
    float* out = (float*)d_out;

    cudaFuncSetAttribute(conv_mma_kernel,
                         cudaFuncAttributeMaxDynamicSharedMemorySize, SMEM_BYTES);

    prep_weights<<<(NTAP * BROWS * N_FILT + 255) / 256, 256>>>(w);

    dim3 grid(NTX, NTY, BATCH);
    conv_mma_kernel<<<grid, 256, SMEM_BYTES>>>(x, bias, out);
}

// round 6
// speedup vs baseline: 4.5626x; 1.4363x over previous
#include <cuda_runtime.h>
#include <cuda_bf16.h>
#include <cuda_fp16.h>
#include <cstdint>

#define H_IN   224
#define H_OUT  220
#define C_IN   32
#define N_FILT 64
#define KS     5
#define NTAP   25
#define BATCH  16

// CTA output tile: 8 rows x 32 cols = 256 pixels (M), N = 64 filters
#define TR 8
#define TC 32
#define HR 12
#define HC 36
#define NLINES (HR * HC)   // 432
#define NTX 7
#define NTY 28

// A halo: [line][a_hi(32ch) | a_lo(32ch)] fp16 = 128B data, 144B stride
#define ASTRIDE 144
#define A_BYTES (NLINES * ASTRIDE)          // 62208
// B per tap: [c=32][f=64] fp16 hi = 128B rows, 144B stride, 3-deep ring
#define BROWS   32
#define BSTRIDE 144
#define B_TILE  (BROWS * BSTRIDE)           // 4608
#define B_OFF   A_BYTES
#define SMEM_BYTES (B_OFF + 3 * B_TILE)     // 76032

__device__ __half g_wh[NTAP * BROWS * N_FILT];   // [tap][c][f] fp16 hi

// ---------------- helpers ----------------
__device__ __forceinline__ uint32_t smem_u32(const void* p) {
    uint32_t a;
    asm("{ .reg .u64 t; cvta.to.shared.u64 t, %1; cvt.u32.u64 %0, t; }" : "=r"(a) : "l"(p));
    return a;
}
__device__ __forceinline__ void cpa16(uint32_t s, const void* g) {
    asm volatile("cp.async.ca.shared.global [%0], [%1], 16;" :: "r"(s), "l"(g));
}
__device__ __forceinline__ void cp_commit() { asm volatile("cp.async.commit_group;"); }
template<int N>
__device__ __forceinline__ void cp_wait() { asm volatile("cp.async.wait_group %0;" :: "n"(N)); }

__device__ __forceinline__ void ldsm4(uint32_t* r, uint32_t a) {
    asm volatile("ldmatrix.sync.aligned.m8n8.x4.shared.b16 {%0,%1,%2,%3}, [%4];"
                 : "=r"(r[0]), "=r"(r[1]), "=r"(r[2]), "=r"(r[3]) : "r"(a));
}
__device__ __forceinline__ void ldsm4t(uint32_t* r, uint32_t a) {
    asm volatile("ldmatrix.sync.aligned.m8n8.x4.trans.shared.b16 {%0,%1,%2,%3}, [%4];"
                 : "=r"(r[0]), "=r"(r[1]), "=r"(r[2]), "=r"(r[3]) : "r"(a));
}
__device__ __forceinline__ void mma16816(float* d, const uint32_t* a,
                                         uint32_t b0, uint32_t b1) {
    asm volatile(
        "mma.sync.aligned.m16n8k16.row.col.f32.f16.f16.f32 "
        "{%0,%1,%2,%3}, {%4,%5,%6,%7}, {%8,%9}, {%0,%1,%2,%3};"
        : "+f"(d[0]), "+f"(d[1]), "+f"(d[2]), "+f"(d[3])
        : "r"(a[0]), "r"(a[1]), "r"(a[2]), "r"(a[3]), "r"(b0), "r"(b1));
}
__device__ __forceinline__ void sts16(uint32_t a, unsigned short v) {
    asm volatile("st.shared.u16 [%0], %1;" :: "r"(a), "h"(v));
}

// ---------------- prep: weights -> fp16 hi, [tap][c][f] ----------------
__global__ void prep_weights(const float* __restrict__ w) {
    int idx = blockIdx.x * blockDim.x + threadIdx.x;
    if (idx >= NTAP * BROWS * N_FILT) return;
    int tap = idx / (BROWS * N_FILT);
    int rem = idx - tap * (BROWS * N_FILT);
    int c = rem >> 6, f = rem & 63;
    g_wh[idx] = __float2half(w[(f * C_IN + c) * (KS * KS) + tap]);
}

// ---------------- main kernel ----------------
__global__ __launch_bounds__(256, 2)
void conv_mma_kernel(const float* __restrict__ x,
                     const float* __restrict__ bias,
                     float* __restrict__ out)
{
    extern __shared__ __align__(128) char smem[];
    const uint32_t sb = smem_u32(smem);

    const int tid = threadIdx.x;
    const int wid = tid >> 5, lid = tid & 31;
    const int g = lid >> 2, c4 = lid & 3;

    const int x0 = blockIdx.x * TC;
    const int y0 = blockIdx.y * TR;
    const int b  = blockIdx.z;

    // stage B hi tile: 32 rows x 128B = exactly 256 x 16B chunks
    auto stageB = [&](int tap, int buf) {
        int row = tid >> 3, seg = tid & 7;
        cpa16(sb + B_OFF + buf * B_TILE + row * BSTRIDE + seg * 16,
              g_wh + (size_t)tap * BROWS * N_FILT + row * N_FILT + seg * 8);
        cp_commit();
    };

    stageB(0, 0);
    stageB(1, 1);

    // ---- build A halo once: fp32 -> fp16 hi/lo ----
    {
        const float* xb = x + (size_t)b * C_IN * H_IN * H_IN;
        #pragma unroll
        for (int j = 0; j < (NLINES * C_IN) / 256; ++j) {   // 54 iters
            int idx = tid + j * 256;
            int c   = idx / NLINES;
            int line = idx - c * NLINES;
            int hy = line / HC, hx = line - hy * HC;
            int gy = y0 + hy, gx = x0 + hx;
            float v = 0.0f;
            if (gy < H_IN && gx < H_IN)
                v = xb[((size_t)c * H_IN + gy) * H_IN + gx];
            __half hi = __float2half(v);
            __half lo = __float2half(v - __half2float(hi));
            uint32_t base = sb + line * ASTRIDE + c * 2;
            sts16(base,      __half_as_ushort(hi));
            sts16(base + 64, __half_as_ushort(lo));
        }
    }

    // accumulators
    float acc[2][8][4];
    #pragma unroll
    for (int mb = 0; mb < 2; ++mb)
        #pragma unroll
        for (int ns = 0; ns < 8; ++ns)
            #pragma unroll
            for (int q = 0; q < 4; ++q) acc[mb][ns][q] = 0.0f;

    const int lrow = lid & 15;
    const int lcol = lid >> 4;
    const uint32_t b_lane = sb + B_OFF + lrow * BSTRIDE + lcol * 16;

    for (int tap = 0; tap < NTAP; ++tap) {
        // wait for B[tap] (<=1 younger group pending), then barrier:
        // also guarantees every warp finished reading B[(tap-1)%3]
        if (tap + 1 < NTAP) cp_wait<1>(); else cp_wait<0>();
        __syncthreads();
        if (tap + 2 < NTAP) stageB(tap + 2, (tap + 2) % 3);

        const int kh = tap / 5, kw = tap - kh * 5;
        const uint32_t a_lane = sb + (uint32_t)(((wid + kh) * HC + kw + lrow) * ASTRIDE)
                              + lcol * 16;
        const uint32_t b_tap = b_lane + (tap % 3) * B_TILE;

        // B fragments: 2 k-steps (c0-15, c16-31), reused for lo k-steps
        uint32_t bfr[2][4][4];
        #pragma unroll
        for (int ks = 0; ks < 2; ++ks)
            #pragma unroll
            for (int np = 0; np < 4; ++np)
                ldsm4t(bfr[ks][np], b_tap + ks * 16 * BSTRIDE + np * 32);

        #pragma unroll
        for (int kk = 0; kk < 4; ++kk) {          // 0,1: a_hi ; 2,3: a_lo
            uint32_t afr[2][4];
            ldsm4(afr[0], a_lane + kk * 32);
            ldsm4(afr[1], a_lane + 16 * ASTRIDE + kk * 32);
            const int bs = kk & 1;
            #pragma unroll
            for (int np = 0; np < 4; ++np) {
                mma16816(acc[0][2 * np + 0], afr[0], bfr[bs][np][0], bfr[bs][np][1]);
                mma16816(acc[0][2 * np + 1], afr[0], bfr[bs][np][2], bfr[bs][np][3]);
                mma16816(acc[1][2 * np + 0], afr[1], bfr[bs][np][0], bfr[bs][np][1]);
                mma16816(acc[1][2 * np + 1], afr[1], bfr[bs][np][2], bfr[bs][np][3]);
            }
        }
    }

    // ---- epilogue ----
    const int oy = y0 + wid;
    if (oy >= H_OUT) return;

    float bv[8][2];
    #pragma unroll
    for (int ns = 0; ns < 8; ++ns) {
        bv[ns][0] = bias[ns * 8 + 2 * c4];
        bv[ns][1] = bias[ns * 8 + 2 * c4 + 1];
    }

    #pragma unroll
    for (int mb = 0; mb < 2; ++mb) {
        #pragma unroll
        for (int h = 0; h < 2; ++h) {
            int i = mb * 16 + h * 8 + g;
            int ox = x0 + i;
            if (ox >= H_OUT) continue;
            size_t base = (((size_t)b * N_FILT) * H_OUT + oy) * H_OUT + ox;
            #pragma unroll
            for (int ns = 0; ns < 8; ++ns) {
                int f = ns * 8 + 2 * c4;
                out[base + (size_t)f * H_OUT * H_OUT] =
                    acc[mb][ns][2 * h + 0] + bv[ns][0];
                out[base + (size_t)(f + 1) * H_OUT * H_OUT] =
                    acc[mb][ns][2 * h + 1] + bv[ns][1];
            }
        }
    }
}

extern "C" void kernel_launch(void* const* d_in, const int* in_sizes, int n_in,
                              void* d_out, int out_size) {
    const float* x    = (const float*)d_in[0];
    const float* w    = (const float*)d_in[1];
    const float* bias = (const float*)d_in[2];
    float* out = (float*)d_out;

    cudaFuncSetAttribute(conv_mma_kernel,
                         cudaFuncAttributeMaxDynamicSharedMemorySize, SMEM_BYTES);

    prep_weights<<<(NTAP * BROWS * N_FILT + 255) / 256, 256>>>(w);

    dim3 grid(NTX, NTY, BATCH);
    conv_mma_kernel<<<grid, 256, SMEM_BYTES>>>(x, bias, out);
}

// round 7
// speedup vs baseline: 7.2983x; 1.5996x over previous
#include <cuda_runtime.h>
#include <cuda_fp16.h>
#include <cstdint>

#define H_IN   224
#define H_OUT  220
#define C_IN   32
#define N_FILT 64
#define KS     5
#define NTAP   25
#define BATCH  16

#define TR 8
#define TC 32
#define HR 12
#define HC 36
#define NLINES (HR * HC)   // 432
#define NTX 7
#define NTY 28

// A halo: [line][32ch fp16 hi] = 64B data, 80B stride (bank-clean for ldmatrix)
#define ASTRIDE 80
#define A_BYTES (NLINES * ASTRIDE)          // 34560
// B per tap: fragment-order layout, 4096B, 6-deep ring
#define B_TILE  4096
#define B_OFF   A_BYTES
#define SMEM_BYTES (B_OFF + 6 * B_TILE)     // 59136

__device__ __half g_wf[NTAP * 2048];   // [tap][frag-order 2048 halfs]

// ---------------- helpers ----------------
__device__ __forceinline__ uint32_t smem_u32(const void* p) {
    uint32_t a;
    asm("{ .reg .u64 t; cvta.to.shared.u64 t, %1; cvt.u32.u64 %0, t; }" : "=r"(a) : "l"(p));
    return a;
}
__device__ __forceinline__ void cpa16(uint32_t s, const void* g) {
    asm volatile("cp.async.ca.shared.global [%0], [%1], 16;" :: "r"(s), "l"(g));
}
__device__ __forceinline__ void cp_commit() { asm volatile("cp.async.commit_group;"); }
template<int N>
__device__ __forceinline__ void cp_wait() { asm volatile("cp.async.wait_group %0;" :: "n"(N)); }

__device__ __forceinline__ void ldsm4(uint32_t* r, uint32_t a) {
    asm volatile("ldmatrix.sync.aligned.m8n8.x4.shared.b16 {%0,%1,%2,%3}, [%4];"
                 : "=r"(r[0]), "=r"(r[1]), "=r"(r[2]), "=r"(r[3]) : "r"(a));
}
__device__ __forceinline__ void ldsv4(uint32_t* r, uint32_t a) {
    asm volatile("ld.shared.v4.u32 {%0,%1,%2,%3}, [%4];"
                 : "=r"(r[0]), "=r"(r[1]), "=r"(r[2]), "=r"(r[3]) : "r"(a));
}
__device__ __forceinline__ void mma16816(float* d, const uint32_t* a,
                                         uint32_t b0, uint32_t b1) {
    asm volatile(
        "mma.sync.aligned.m16n8k16.row.col.f32.f16.f16.f32 "
        "{%0,%1,%2,%3}, {%4,%5,%6,%7}, {%8,%9}, {%0,%1,%2,%3};"
        : "+f"(d[0]), "+f"(d[1]), "+f"(d[2]), "+f"(d[3])
        : "r"(a[0]), "r"(a[1]), "r"(a[2]), "r"(a[3]), "r"(b0), "r"(b1));
}
__device__ __forceinline__ void sts16(uint32_t a, unsigned short v) {
    asm volatile("st.shared.u16 [%0], %1;" :: "r"(a), "h"(v));
}

// ---------------- prep: weights -> fp16 hi in mma-fragment order ----------------
// word index within tap: ((ks*4+np)*32 + lane)*4 + r  (uint32 words, 1024/tap)
// reg r of mma B-frag (lane): c = ks*16 + (lane%4)*2 + (r&1 ? 8 : 0)
//                             f = np*16 + lane/4     + (r&2 ? 8 : 0)
__global__ void prep_weights(const float* __restrict__ w) {
    int idx = blockIdx.x * blockDim.x + threadIdx.x;     // word id
    if (idx >= NTAP * 1024) return;
    int tap = idx >> 10;
    int rem = idx & 1023;
    int grp  = rem >> 7;             // ks*4+np
    int lane = (rem >> 2) & 31;
    int r    = rem & 3;
    int ks = grp >> 2, np = grp & 3;
    int c = ks * 16 + (lane & 3) * 2 + ((r & 1) ? 8 : 0);
    int f = np * 16 + (lane >> 2)   + ((r & 2) ? 8 : 0);
    __half h0 = __float2half(w[(f * C_IN + c    ) * (KS * KS) + tap]);
    __half h1 = __float2half(w[(f * C_IN + c + 1) * (KS * KS) + tap]);
    __half2* dst = reinterpret_cast<__half2*>(g_wf + (size_t)tap * 2048);
    dst[rem] = __halves2half2(h0, h1);
}

// ---------------- main kernel ----------------
__global__ __launch_bounds__(256, 2)
void conv_mma_kernel(const float* __restrict__ x,
                     const float* __restrict__ bias,
                     float* __restrict__ out)
{
    extern __shared__ __align__(128) char smem[];
    const uint32_t sb = smem_u32(smem);

    const int tid = threadIdx.x;
    const int wid = tid >> 5, lid = tid & 31;
    const int g = lid >> 2, c4 = lid & 3;

    const int x0 = blockIdx.x * TC;
    const int y0 = blockIdx.y * TR;
    const int b  = blockIdx.z;

    // stage one B tile: 256 threads x 16B = 4096B
    auto stageB = [&](int tap) {
        cpa16(sb + B_OFF + (tap % 6) * B_TILE + tid * 16,
              g_wf + (size_t)tap * 2048 + tid * 8);
    };

    stageB(0); stageB(1); cp_commit();
    stageB(2); stageB(3); cp_commit();

    // ---- build A halo (hi only) ----
    {
        const float* xb = x + (size_t)b * C_IN * H_IN * H_IN;
        #pragma unroll
        for (int j = 0; j < (NLINES * C_IN) / 256; ++j) {   // 54 iters
            int idx = tid + j * 256;
            int c   = idx / NLINES;
            int line = idx - c * NLINES;
            int hy = line / HC, hx = line - hy * HC;
            int gy = y0 + hy, gx = x0 + hx;
            float v = 0.0f;
            if (gy < H_IN && gx < H_IN)
                v = xb[((size_t)c * H_IN + gy) * H_IN + gx];
            sts16(sb + line * ASTRIDE + c * 2,
                  __half_as_ushort(__float2half(v)));
        }
    }

    float acc[2][8][4];
    #pragma unroll
    for (int mb = 0; mb < 2; ++mb)
        #pragma unroll
        for (int ns = 0; ns < 8; ++ns)
            #pragma unroll
            for (int q = 0; q < 4; ++q) acc[mb][ns][q] = 0.0f;

    const int lrow = lid & 15;
    const int lcol = lid >> 4;

    for (int tap = 0; tap < NTAP; tap += 2) {
        if (tap + 2 < NTAP) cp_wait<1>(); else cp_wait<0>();
        __syncthreads();
        {
            bool st = false;
            if (tap + 4 < NTAP) { stageB(tap + 4); st = true; }
            if (tap + 5 < NTAP) { stageB(tap + 5); }
            if (st) cp_commit();
        }

        #pragma unroll
        for (int t2 = 0; t2 < 2; ++t2) {
            const int tp = tap + t2;
            if (tp >= NTAP) break;
            const int kh = tp / 5, kw = tp - kh * 5;
            const uint32_t a_lane = sb
                + (uint32_t)(((wid + kh) * HC + kw + lrow) * ASTRIDE) + lcol * 16;
            const uint32_t b_base = sb + B_OFF + (tp % 6) * B_TILE + lid * 16;

            #pragma unroll
            for (int kk = 0; kk < 2; ++kk) {              // k-halves of C=32
                uint32_t afr[2][4];
                ldsm4(afr[0], a_lane + kk * 32);
                ldsm4(afr[1], a_lane + 16 * ASTRIDE + kk * 32);
                #pragma unroll
                for (int np = 0; np < 4; ++np) {
                    uint32_t bq[4];
                    ldsv4(bq, b_base + (kk * 4 + np) * 512);
                    mma16816(acc[0][2 * np + 0], afr[0], bq[0], bq[1]);
                    mma16816(acc[0][2 * np + 1], afr[0], bq[2], bq[3]);
                    mma16816(acc[1][2 * np + 0], afr[1], bq[0], bq[1]);
                    mma16816(acc[1][2 * np + 1], afr[1], bq[2], bq[3]);
                }
            }
        }
    }

    // ---- epilogue ----
    const int oy = y0 + wid;
    if (oy >= H_OUT) return;

    float bv[8][2];
    #pragma unroll
    for (int ns = 0; ns < 8; ++ns) {
        bv[ns][0] = bias[ns * 8 + 2 * c4];
        bv[ns][1] = bias[ns * 8 + 2 * c4 + 1];
    }

    #pragma unroll
    for (int mb = 0; mb < 2; ++mb) {
        #pragma unroll
        for (int h = 0; h < 2; ++h) {
            int i = mb * 16 + h * 8 + g;
            int ox = x0 + i;
            if (ox >= H_OUT) continue;
            size_t base = (((size_t)b * N_FILT) * H_OUT + oy) * H_OUT + ox;
            #pragma unroll
            for (int ns = 0; ns < 8; ++ns) {
                int f = ns * 8 + 2 * c4;
                out[base + (size_t)f * H_OUT * H_OUT] =
                    acc[mb][ns][2 * h + 0] + bv[ns][0];
                out[base + (size_t)(f + 1) * H_OUT * H_OUT] =
                    acc[mb][ns][2 * h + 1] + bv[ns][1];
            }
        }
    }
}

extern "C" void kernel_launch(void* const* d_in, const int* in_sizes, int n_in,
                              void* d_out, int out_size) {
    const float* x    = (const float*)d_in[0];
    const float* w    = (const float*)d_in[1];
    const float* bias = (const float*)d_in[2];
    float* out = (float*)d_out;

    cudaFuncSetAttribute(conv_mma_kernel,
                         cudaFuncAttributeMaxDynamicSharedMemorySize, SMEM_BYTES);

    prep_weights<<<(NTAP * 1024 + 255) / 256, 256>>>(w);

    dim3 grid(NTX, NTY, BATCH);
    conv_mma_kernel<<<grid, 256, SMEM_BYTES>>>(x, bias, out);
}

// round 8
// speedup vs baseline: 7.4213x; 1.0169x over previous
#include <cuda_runtime.h>
#include <cuda_fp16.h>
#include <cstdint>

#define H_IN   224
#define H_OUT  220
#define C_IN   32
#define N_FILT 64
#define KS     5
#define NTAP   25
#define BATCH  16

#define TR 16              // output rows per CTA (one per warp)
#define TC 32
#define HR 20              // TR + 4
#define HC 36
#define NLINES (HR * HC)   // 720
#define NTX 7
#define NTY 14             // ceil(220/16)

// A halo: [line][32ch fp16] = 64B data, 80B stride (conflict-free ldmatrix)
#define ASTRIDE 80
#define A_BYTES (NLINES * ASTRIDE)          // 57600
// B: ALL taps resident, fragment order, 4096B per tap
#define B_TILE  4096
#define B_OFF   A_BYTES
#define SMEM_BYTES (B_OFF + NTAP * B_TILE)  // 160000

__device__ __half g_wf[NTAP * 2048];   // [tap][frag-order 2048 halfs]

// ---------------- helpers ----------------
__device__ __forceinline__ uint32_t smem_u32(const void* p) {
    uint32_t a;
    asm("{ .reg .u64 t; cvta.to.shared.u64 t, %1; cvt.u32.u64 %0, t; }" : "=r"(a) : "l"(p));
    return a;
}
__device__ __forceinline__ void cpa16(uint32_t s, const void* g) {
    asm volatile("cp.async.ca.shared.global [%0], [%1], 16;" :: "r"(s), "l"(g));
}
__device__ __forceinline__ void cp_commit() { asm volatile("cp.async.commit_group;"); }
__device__ __forceinline__ void cp_wait0()  { asm volatile("cp.async.wait_group 0;"); }

__device__ __forceinline__ void ldsm4(uint32_t* r, uint32_t a) {
    asm volatile("ldmatrix.sync.aligned.m8n8.x4.shared.b16 {%0,%1,%2,%3}, [%4];"
                 : "=r"(r[0]), "=r"(r[1]), "=r"(r[2]), "=r"(r[3]) : "r"(a));
}
__device__ __forceinline__ void ldsv4(uint32_t* r, uint32_t a) {
    asm volatile("ld.shared.v4.u32 {%0,%1,%2,%3}, [%4];"
                 : "=r"(r[0]), "=r"(r[1]), "=r"(r[2]), "=r"(r[3]) : "r"(a));
}
__device__ __forceinline__ void mma16816(float* d, const uint32_t* a,
                                         uint32_t b0, uint32_t b1) {
    asm volatile(
        "mma.sync.aligned.m16n8k16.row.col.f32.f16.f16.f32 "
        "{%0,%1,%2,%3}, {%4,%5,%6,%7}, {%8,%9}, {%0,%1,%2,%3};"
        : "+f"(d[0]), "+f"(d[1]), "+f"(d[2]), "+f"(d[3])
        : "r"(a[0]), "r"(a[1]), "r"(a[2]), "r"(a[3]), "r"(b0), "r"(b1));
}
__device__ __forceinline__ void sts16(uint32_t a, unsigned short v) {
    asm volatile("st.shared.u16 [%0], %1;" :: "r"(a), "h"(v));
}

// ---------------- prep: weights -> fp16 in mma-fragment order ----------------
// word index within tap: ((ks*4+np)*32 + lane)*4 + r
// reg r of mma B-frag (lane): c = ks*16 + (lane%4)*2 + (r&1 ? 8 : 0)
//                             f = np*16 + lane/4     + (r&2 ? 8 : 0)
__global__ void prep_weights(const float* __restrict__ w) {
    int idx = blockIdx.x * blockDim.x + threadIdx.x;
    if (idx >= NTAP * 1024) return;
    int tap = idx >> 10;
    int rem = idx & 1023;
    int grp  = rem >> 7;
    int lane = (rem >> 2) & 31;
    int r    = rem & 3;
    int ks = grp >> 2, np = grp & 3;
    int c = ks * 16 + (lane & 3) * 2 + ((r & 1) ? 8 : 0);
    int f = np * 16 + (lane >> 2)   + ((r & 2) ? 8 : 0);
    __half h0 = __float2half(w[(f * C_IN + c    ) * (KS * KS) + tap]);
    __half h1 = __float2half(w[(f * C_IN + c + 1) * (KS * KS) + tap]);
    __half2* dst = reinterpret_cast<__half2*>(g_wf + (size_t)tap * 2048);
    dst[rem] = __halves2half2(h0, h1);
}

// ---------------- main kernel ----------------
__global__ __launch_bounds__(512, 1)
void conv_mma_kernel(const float* __restrict__ x,
                     const float* __restrict__ bias,
                     float* __restrict__ out)
{
    extern __shared__ __align__(128) char smem[];
    const uint32_t sb = smem_u32(smem);

    const int tid = threadIdx.x;
    const int wid = tid >> 5, lid = tid & 31;
    const int g = lid >> 2, c4 = lid & 3;

    const int x0 = blockIdx.x * TC;
    const int y0 = blockIdx.y * TR;
    const int b  = blockIdx.z;

    // ---- stage ALL B tiles (100KB linear copy, async) ----
    #pragma unroll
    for (int j = 0; j < 13; ++j) {
        int idx = tid + j * 512;                       // 6400 x 16B chunks
        if (idx < NTAP * 256)
            cpa16(sb + B_OFF + idx * 16, g_wf + (size_t)idx * 8);
    }
    cp_commit();

    // ---- build A halo (fp32 -> fp16) ----
    {
        const float* xb = x + (size_t)b * C_IN * H_IN * H_IN;
        #pragma unroll
        for (int j = 0; j < (NLINES * C_IN) / 512; ++j) {   // 45 iters
            int idx = tid + j * 512;
            int c   = idx / NLINES;
            int line = idx - c * NLINES;
            int hy = line / HC, hx = line - hy * HC;
            int gy = y0 + hy, gx = x0 + hx;
            float v = 0.0f;
            if (gy < H_IN && gx < H_IN)
                v = xb[((size_t)c * H_IN + gy) * H_IN + gx];
            sts16(sb + line * ASTRIDE + c * 2,
                  __half_as_ushort(__float2half(v)));
        }
    }
    cp_wait0();
    __syncthreads();      // the ONLY barrier

    float acc[2][8][4];
    #pragma unroll
    for (int mb = 0; mb < 2; ++mb)
        #pragma unroll
        for (int ns = 0; ns < 8; ++ns)
            #pragma unroll
            for (int q = 0; q < 4; ++q) acc[mb][ns][q] = 0.0f;

    const int lrow = lid & 15;
    const int lcol = lid >> 4;
    const uint32_t a_base0 = sb + (uint32_t)((wid * HC + lrow) * ASTRIDE) + lcol * 16;
    const uint32_t b_base0 = sb + B_OFF + lid * 16;

    #pragma unroll
    for (int kh = 0; kh < 5; ++kh) {
        #pragma unroll
        for (int kw = 0; kw < 5; ++kw) {
            const int tap = kh * 5 + kw;
            const uint32_t a_lane = a_base0 + (uint32_t)((kh * HC + kw) * ASTRIDE);
            const uint32_t b_tap  = b_base0 + tap * B_TILE;

            // hoist all 4 A ldmatrix (MLP), B loads interleave with mma
            uint32_t afr[2][2][4];               // [kk][m-block][4]
            ldsm4(afr[0][0], a_lane);
            ldsm4(afr[0][1], a_lane + 16 * ASTRIDE);
            ldsm4(afr[1][0], a_lane + 32);
            ldsm4(afr[1][1], a_lane + 16 * ASTRIDE + 32);

            #pragma unroll
            for (int kk = 0; kk < 2; ++kk) {
                #pragma unroll
                for (int np = 0; np < 4; ++np) {
                    uint32_t bq[4];
                    ldsv4(bq, b_tap + (kk * 4 + np) * 512);
                    mma16816(acc[0][2 * np + 0], afr[kk][0], bq[0], bq[1]);
                    mma16816(acc[0][2 * np + 1], afr[kk][0], bq[2], bq[3]);
                    mma16816(acc[1][2 * np + 0], afr[kk][1], bq[0], bq[1]);
                    mma16816(acc[1][2 * np + 1], afr[kk][1], bq[2], bq[3]);
                }
            }
        }
    }

    // ---- epilogue ----
    const int oy = y0 + wid;
    if (oy >= H_OUT) return;

    float bv[8][2];
    #pragma unroll
    for (int ns = 0; ns < 8; ++ns) {
        bv[ns][0] = bias[ns * 8 + 2 * c4];
        bv[ns][1] = bias[ns * 8 + 2 * c4 + 1];
    }

    #pragma unroll
    for (int mb = 0; mb < 2; ++mb) {
        #pragma unroll
        for (int h = 0; h < 2; ++h) {
            int i = mb * 16 + h * 8 + g;
            int ox = x0 + i;
            if (ox >= H_OUT) continue;
            size_t base = (((size_t)b * N_FILT) * H_OUT + oy) * H_OUT + ox;
            #pragma unroll
            for (int ns = 0; ns < 8; ++ns) {
                int f = ns * 8 + 2 * c4;
                out[base + (size_t)f * H_OUT * H_OUT] =
                    acc[mb][ns][2 * h + 0] + bv[ns][0];
                out[base + (size_t)(f + 1) * H_OUT * H_OUT] =
                    acc[mb][ns][2 * h + 1] + bv[ns][1];
            }
        }
    }
}

extern "C" void kernel_launch(void* const* d_in, const int* in_sizes, int n_in,
                              void* d_out, int out_size) {
    const float* x    = (const float*)d_in[0];
    const float* w    = (const float*)d_in[1];
    const float* bias = (const float*)d_in[2];
    float* out = (float*)d_out;

    cudaFuncSetAttribute(conv_mma_kernel,
                         cudaFuncAttributeMaxDynamicSharedMemorySize, SMEM_BYTES);

    prep_weights<<<(NTAP * 1024 + 255) / 256, 256>>>(w);

    dim3 grid(NTX, NTY, BATCH);
    conv_mma_kernel<<<grid, 512, SMEM_BYTES>>>(x, bias, out);
}